// round 15
// baseline (speedup 1.0000x reference)
#include <cuda_runtime.h>
#include <cstdint>

#define DIM   64
#define ODIM  16
#define NMAX  100000
#define EMAX  1600000
#define GMAX  512
#define NB_SCAN 512

#define PFX (1ULL << 63)
#define AGG (1ULL << 62)

// ---- scratch (no allocations allowed; __device__ globals per rules) ----
// INVARIANT: d_deg all-zero at kernel_launch entry (zero at module load;
// scan_lb_k re-zeroes after reading). d_sstate re-zeroed by count_k (block 130).
__device__ __align__(16) float d_agg[(size_t)NMAX * DIM];
__device__ __align__(16) float d_h1 [(size_t)NMAX * DIM];
__device__ __align__(16) float d_pool[(size_t)GMAX * DIM];
__device__ float d_gcnt[GMAX];
__device__ int d_deg[NMAX];
__device__ int d_off[NMAX + 1];
__device__ int d_cur[NMAX];
__device__ int d_col[EMAX];
__device__ unsigned long long d_sstate[NB_SCAN];

// ---- helpers ----
__device__ __forceinline__ void red_add_v4(float* p, float4 v) {
    asm volatile("red.global.add.v4.f32 [%0], {%1,%2,%3,%4};"
                 :: "l"(p), "f"(v.x), "f"(v.y), "f"(v.z), "f"(v.w) : "memory");
}
__device__ __forceinline__ void unpack2(unsigned long long v, float& lo, float& hi) {
    unsigned int a, b;
    asm("mov.b64 {%0,%1}, %2;" : "=r"(a), "=r"(b) : "l"(v));
    lo = __uint_as_float(a); hi = __uint_as_float(b);
}
#define FMA2(acc, a, b) \
    asm("fma.rn.f32x2 %0, %1, %2, %0;" : "+l"(acc) : "l"(a), "l"(b))

// ---- launch 1: degree count + pool zero + gcnt + scan-state zero ----
__global__ void count_k(const int* __restrict__ ei, int E, int T,
                        const int* __restrict__ batch, int n, int G) {
    int b = blockIdx.x;
    int tid = threadIdx.x;
    int i = b * 256 + tid;
    int e0 = i, e1 = i + T, e2 = i + 2 * T, e3 = i + 3 * T;
    int v0 = (e0 < E) ? __ldg(&ei[E + e0]) : -1;
    int v1 = (e1 < E) ? __ldg(&ei[E + e1]) : -1;
    int v2 = (e2 < E) ? __ldg(&ei[E + e2]) : -1;
    int v3 = (e3 < E) ? __ldg(&ei[E + e3]) : -1;
    if (v0 >= 0) atomicAdd(&d_deg[v0], 1);
    if (v1 >= 0) atomicAdd(&d_deg[v1], 1);
    if (v2 >= 0) atomicAdd(&d_deg[v2], 1);
    if (v3 >= 0) atomicAdd(&d_deg[v3], 1);
    if (b < 128) {
        int j = b * 256 + tid;
        if (j < G * DIM) d_pool[j] = 0.f;
    } else if (b < 130) {
        int g = (b - 128) * 256 + tid;
        if (g < G) {
            int lo = 0, hi = n;
            while (lo < hi) { int m = (lo + hi) >> 1; if (batch[m] < g) lo = m + 1; else hi = m; }
            int lo2 = lo, hi2 = n;
            while (lo2 < hi2) { int m = (lo2 + hi2) >> 1; if (batch[m] < g + 1) lo2 = m + 1; else hi2 = m; }
            d_gcnt[g] = (float)(lo2 - lo);
        }
    } else if (b == 130) {
        d_sstate[tid] = 0ULL;
        d_sstate[tid + 256] = 0ULL;
    }
}

// ---- launch 2: single-pass decoupled-lookback exclusive scan ----
__global__ __launch_bounds__(256)
void scan_lb_k(int n, int E) {
    __shared__ int wsc[8];
    __shared__ int sbase;
    int b = blockIdx.x, tid = threadIdx.x, lane = tid & 31, wid = tid >> 5;
    int i = b * 256 + tid;
    int v = 0;
    if (i < n) { v = d_deg[i]; d_deg[i] = 0; }
    int s = v;
#pragma unroll
    for (int o = 1; o < 32; o <<= 1) {
        int t = __shfl_up_sync(0xffffffffu, s, o);
        if (lane >= o) s += t;
    }
    if (lane == 31) wsc[wid] = s;
    __syncthreads();
    if (wid == 0 && lane < 8) {
        int ws = wsc[lane];
#pragma unroll
        for (int o = 1; o < 8; o <<= 1) {
            int t = __shfl_up_sync(0xffu, ws, o);
            if (lane >= o) ws += t;
        }
        wsc[lane] = ws;
    }
    __syncthreads();
    int incl = s + (wid ? wsc[wid - 1] : 0);
    int total = wsc[7];

    if (tid == 0)
        atomicExch(&d_sstate[b], (b == 0 ? PFX : AGG) | (unsigned long long)(unsigned)total);

    if (b == 0) {
        if (tid == 0) sbase = 0;
    } else if (wid == 0) {
        unsigned long long run = 0;
        int j = b - 1;
        while (true) {
            int idx = j - lane;
            unsigned long long w64 = (idx >= 0) ? atomicAdd(&d_sstate[idx], 0ULL) : PFX;
            while (__ballot_sync(0xffffffffu, w64 == 0ULL)) {
                if (w64 == 0ULL) w64 = atomicAdd(&d_sstate[idx], 0ULL);
            }
            unsigned pm = __ballot_sync(0xffffffffu, (w64 & PFX) != 0ULL);
            unsigned c;
            if (pm) {
                int fp = __ffs(pm) - 1;
                c = (lane <= fp) ? (unsigned)w64 : 0;
#pragma unroll
                for (int o = 16; o; o >>= 1) c += __shfl_xor_sync(0xffffffffu, c, o);
                run += c;
                break;
            } else {
                c = (unsigned)w64;
#pragma unroll
                for (int o = 16; o; o >>= 1) c += __shfl_xor_sync(0xffffffffu, c, o);
                run += c;
                j -= 32;
            }
        }
        if (lane == 0) {
            atomicExch(&d_sstate[b], PFX | (unsigned long long)(unsigned)(run + (unsigned)total));
            sbase = (int)run;
        }
    }
    __syncthreads();
    int base = sbase;
    if (i < n) { int ex = base + incl - v; d_off[i] = ex; d_cur[i] = ex; }
    if (b == 0 && tid == 0) d_off[n] = E;
}

// ---- launch 3: CSR fill ----
__global__ void fill_k(const int* __restrict__ ei, int E, int T) {
    int i = blockIdx.x * blockDim.x + threadIdx.x;
#pragma unroll
    for (int t = 0; t < 4; t++) {
        int e = i + t * T;
        if (e < E) {
            int s = __ldg(&ei[e]);
            int d = __ldg(&ei[E + e]);
            int p = atomicAdd(&d_cur[d], 1);
            d_col[p] = s;
        }
    }
}

// ---- gather: warp per node; idx coalesced + shfl-broadcast; 8-edge batches ----
__global__ __launch_bounds__(256)
void gather_k(const float* __restrict__ feat, float* __restrict__ agg, int N) {
    int node = (blockIdx.x * 256 + threadIdx.x) >> 5;
    int lane = threadIdx.x & 31;
    if (node >= N) return;
    int beg = d_off[node];
    int end = d_off[node + 1];
    int half = lane >> 4;
    int col4 = lane & 15;
    const float4* f4 = (const float4*)feat;
    float4 acc = make_float4(0.f, 0.f, 0.f, 0.f);
    for (int b = beg; b < end; b += 32) {
        int m = min(32, end - b);
        int idx = (lane < m) ? __ldg(&d_col[b + lane]) : 0;
        int j = 0;
        for (; j + 8 <= m; j += 8) {
            int c0 = __shfl_sync(0xffffffffu, idx, j     + half);
            int c1 = __shfl_sync(0xffffffffu, idx, j + 2 + half);
            int c2 = __shfl_sync(0xffffffffu, idx, j + 4 + half);
            int c3 = __shfl_sync(0xffffffffu, idx, j + 6 + half);
            float4 v0 = __ldg(f4 + (size_t)c0 * 16 + col4);
            float4 v1 = __ldg(f4 + (size_t)c1 * 16 + col4);
            float4 v2 = __ldg(f4 + (size_t)c2 * 16 + col4);
            float4 v3 = __ldg(f4 + (size_t)c3 * 16 + col4);
            acc.x += (v0.x + v1.x) + (v2.x + v3.x);
            acc.y += (v0.y + v1.y) + (v2.y + v3.y);
            acc.z += (v0.z + v1.z) + (v2.z + v3.z);
            acc.w += (v0.w + v1.w) + (v2.w + v3.w);
        }
        for (; j + 2 <= m; j += 2) {
            int c = __shfl_sync(0xffffffffu, idx, j + half);
            float4 v = __ldg(f4 + (size_t)c * 16 + col4);
            acc.x += v.x; acc.y += v.y; acc.z += v.z; acc.w += v.w;
        }
        if (j < m) {
            int c = __shfl_sync(0xffffffffu, idx, m - 1);
            if (half == 0) {
                float4 v = __ldg(f4 + (size_t)c * 16 + col4);
                acc.x += v.x; acc.y += v.y; acc.z += v.z; acc.w += v.w;
            }
        }
    }
    acc.x += __shfl_xor_sync(0xffffffffu, acc.x, 16);
    acc.y += __shfl_xor_sync(0xffffffffu, acc.y, 16);
    acc.z += __shfl_xor_sync(0xffffffffu, acc.z, 16);
    acc.w += __shfl_xor_sync(0xffffffffu, acc.w, 16);
    if (half == 0) {
        float inv = 1.f / (float)max(end - beg, 1);
        acc.x *= inv; acc.y *= inv; acc.z *= inv; acc.w *= inv;
        *(float4*)(agg + (size_t)node * DIM + col4 * 4) = acc;
    }
}

// ---- fused SAGE node update: k-pair packed FMA2, concatenated K=128 GEMM ----
// rows = [agg || x] (dsh, 132-float padded rows), weights = [Wl ; Wr] pre-paired
// in smem: pair(kp,o) at byte kp*512 + ((o>>1)&1)*256 + (o>>2)*16 + (o&1)*8.
// f32x2 lanes hold two k-partials of the SAME output; epilogue sums lo+hi.
// Zero per-iteration MOVs: data pairs come straight from float4 (ulonglong2) loads.
#define DROW 132
__global__ __launch_bounds__(256)
void node_k(const float* __restrict__ xin, const float* __restrict__ agg,
            const float* __restrict__ Wl, const float* __restrict__ bl,
            const float* __restrict__ Wr, float* __restrict__ hout,
            const int* __restrict__ batch, int n_nodes) {
    extern __shared__ __align__(16) float smem[];
    float* wsm = smem;                  // 64 kp * 128 floats = 32 KB
    float* dsh = smem + 8192;           // 64 rows * 132 floats = 33 KB

    int tid = threadIdx.x;
    int nb = blockIdx.x * 64;

    // stage weights pre-paired: Wl -> kp 0..31, Wr -> kp 32..63
    for (int i = tid; i < DIM * DIM; i += 256) {
        int o = i >> 6, k = i & 63;
        int h = (o >> 1) & 1, qq = o >> 2, p = o & 1;
        int f0 = ((k >> 1) << 7) + (h << 6) + (qq << 2) + (p << 1) + (k & 1);
        wsm[f0] = Wl[i];
        wsm[f0 + 32 * 128] = Wr[i];
    }
    // stage data rows: [r][0..63]=agg, [r][64..127]=x
    {
        long long base4 = (long long)nb * 16;
        long long lim = (long long)n_nodes * 16;
        const float4* agg4 = (const float4*)agg;
        const float4* x4   = (const float4*)xin;
        float4 z = make_float4(0.f, 0.f, 0.f, 0.f);
#pragma unroll
        for (int t2 = 0; t2 < 4; t2++) {
            int i = tid + t2 * 256;          // 0..1023: r=i>>4, c4=i&15
            int r = i >> 4, c4 = i & 15;
            long long g = base4 + i;
            *(float4*)(dsh + r * DROW + c4 * 4)      = (g < lim) ? agg4[g] : z;
            *(float4*)(dsh + r * DROW + 64 + c4 * 4) = (g < lim) ? x4[g]   : z;
        }
    }
    __syncthreads();

    int q = tid & 15;
    int s = tid >> 4;
    float4 bq = *(const float4*)(bl + 4 * q);

    const float* r0p = dsh + (s     ) * DROW;
    const float* r1p = dsh + (s + 16) * DROW;
    const float* r2p = dsh + (s + 32) * DROW;
    const float* r3p = dsh + (s + 48) * DROW;
    const float* wq  = wsm + q * 4;

    unsigned long long acc[4][4] = {{0,0,0,0},{0,0,0,0},{0,0,0,0},{0,0,0,0}};

#pragma unroll
    for (int t = 0; t < 32; t++) {      // t = float4 group = 2 kp
        ulonglong2 d0 = *(const ulonglong2*)(r0p + t * 4);
        ulonglong2 d1 = *(const ulonglong2*)(r1p + t * 4);
        ulonglong2 d2 = *(const ulonglong2*)(r2p + t * 4);
        ulonglong2 d3 = *(const ulonglong2*)(r3p + t * 4);
#pragma unroll
        for (int hf = 0; hf < 2; hf++) {
            const float* wp = wq + (2 * t + hf) * 128;
            ulonglong2 wA = *(const ulonglong2*)(wp);        // outputs 4q, 4q+1
            ulonglong2 wB = *(const ulonglong2*)(wp + 64);   // outputs 4q+2, 4q+3
            unsigned long long v0 = hf ? d0.y : d0.x;
            unsigned long long v1 = hf ? d1.y : d1.x;
            unsigned long long v2 = hf ? d2.y : d2.x;
            unsigned long long v3 = hf ? d3.y : d3.x;
            FMA2(acc[0][0], v0, wA.x); FMA2(acc[0][1], v0, wA.y);
            FMA2(acc[0][2], v0, wB.x); FMA2(acc[0][3], v0, wB.y);
            FMA2(acc[1][0], v1, wA.x); FMA2(acc[1][1], v1, wA.y);
            FMA2(acc[1][2], v1, wB.x); FMA2(acc[1][3], v1, wB.y);
            FMA2(acc[2][0], v2, wA.x); FMA2(acc[2][1], v2, wA.y);
            FMA2(acc[2][2], v2, wB.x); FMA2(acc[2][3], v2, wB.y);
            FMA2(acc[3][0], v3, wA.x); FMA2(acc[3][1], v3, wA.y);
            FMA2(acc[3][2], v3, wB.x); FMA2(acc[3][3], v3, wB.y);
        }
    }

#pragma unroll
    for (int j = 0; j < 4; j++) {
        int node = nb + s + 16 * j;
        if (node >= n_nodes) continue;
        float a0, b0, a1, b1, a2, b2, a3, b3;
        unpack2(acc[j][0], a0, b0);
        unpack2(acc[j][1], a1, b1);
        unpack2(acc[j][2], a2, b2);
        unpack2(acc[j][3], a3, b3);
        float4 res;
        res.x = fmaxf((a0 + b0) + bq.x, 0.f);
        res.y = fmaxf((a1 + b1) + bq.y, 0.f);
        res.z = fmaxf((a2 + b2) + bq.z, 0.f);
        res.w = fmaxf((a3 + b3) + bq.w, 0.f);
        if (batch) {
            int g = batch[node];
            red_add_v4(&d_pool[(size_t)g * DIM + 4 * q], res);
        } else {
            *(float4*)&hout[(size_t)node * DIM + 4 * q] = res;
        }
    }
}
#define NODE_SMEM (32768 + 64 * DROW * 4)

// ---- pooled mean -> fc -> log_softmax ----
__global__ void final_k(const float* __restrict__ fcW, const float* __restrict__ fcb,
                        float* __restrict__ out, int G) {
    int g = blockIdx.x * blockDim.x + threadIdx.x;
    if (g >= G) return;
    float inv = 1.f / fmaxf(d_gcnt[g], 1.f);
    float p[DIM];
    const float* pr = &d_pool[(size_t)g * DIM];
#pragma unroll
    for (int k = 0; k < DIM; k++) p[k] = pr[k] * inv;
    float lg[ODIM];
#pragma unroll
    for (int o = 0; o < ODIM; o++) {
        float s = fcb[o];
        const float* w = &fcW[o * DIM];
#pragma unroll
        for (int k = 0; k < DIM; k++) s = fmaf(p[k], w[k], s);
        lg[o] = s;
    }
    float m = lg[0];
#pragma unroll
    for (int o = 1; o < ODIM; o++) m = fmaxf(m, lg[o]);
    float se = 0.f;
#pragma unroll
    for (int o = 0; o < ODIM; o++) se += expf(lg[o] - m);
    float lse = m + logf(se);
#pragma unroll
    for (int o = 0; o < ODIM; o++) out[g * ODIM + o] = lg[o] - lse;
}

extern "C" void kernel_launch(void* const* d_in, const int* in_sizes, int n_in,
                              void* d_out, int out_size) {
    const float* x   = (const float*)d_in[0];
    const float* W1l = (const float*)d_in[1];
    const float* b1  = (const float*)d_in[2];
    const float* W1r = (const float*)d_in[3];
    const float* W2l = (const float*)d_in[4];
    const float* b2  = (const float*)d_in[5];
    const float* W2r = (const float*)d_in[6];
    const float* fcW = (const float*)d_in[7];
    const float* fcb = (const float*)d_in[8];
    const int* ei    = (const int*)d_in[9];     // int32 (JAX x64 disabled)
    const int* batch = (const int*)d_in[10];

    int N = in_sizes[10];
    int E = in_sizes[9] / 2;
    int G = out_size / ODIM;
    int NB = (N + 255) / 256;
    int T  = (E + 3) / 4;
    int NBE4 = (T + 255) / 256;

    float *agg, *h1;
    cudaGetSymbolAddress((void**)&agg, d_agg);
    cudaGetSymbolAddress((void**)&h1,  d_h1);

    static int smem_set = 0;   // sticky attribute; host-side, not a graph op
    if (!smem_set) {
        cudaFuncSetAttribute(node_k, cudaFuncAttributeMaxDynamicSharedMemorySize, NODE_SMEM);
        smem_set = 1;
    }

    // CSR build (single-pass lookback scan; invariants restored each replay)
    count_k<<<NBE4, 256>>>(ei, E, T, batch, N, G);   // 1
    scan_lb_k<<<NB, 256>>>(N, E);                    // 2
    fill_k<<<NBE4, 256>>>(ei, E, T);                 // 3

    // layer 1
    gather_k<<<(N + 7) / 8, 256>>>(x, agg, N);       // 4
    node_k<<<(N + 63) / 64, 256, NODE_SMEM>>>(x, agg, W1l, b1, W1r, h1, nullptr, N);  // 5

    // layer 2
    gather_k<<<(N + 7) / 8, 256>>>(h1, agg, N);
    node_k<<<(N + 63) / 64, 256, NODE_SMEM>>>(h1, agg, W2l, b2, W2r, nullptr, batch, N);

    // pool -> fc -> log_softmax
    final_k<<<(G + 255) / 256, 256>>>(fcW, fcb, (float*)d_out, G);
}

// round 16
// speedup vs baseline: 1.1160x; 1.1160x over previous
#include <cuda_runtime.h>
#include <cstdint>

#define DIM   64
#define ODIM  16
#define NMAX  100000
#define EMAX  1600000
#define GMAX  512
#define NB_SCAN 512

#define PFX (1ULL << 63)
#define AGG (1ULL << 62)

// ---- scratch (no allocations allowed; __device__ globals per rules) ----
// INVARIANT: d_deg all-zero at kernel_launch entry (zero at module load;
// scan_lb_k re-zeroes after reading). d_sstate re-zeroed by count_k (block 130).
__device__ __align__(16) float d_agg[(size_t)NMAX * DIM];
__device__ __align__(16) float d_h1 [(size_t)NMAX * DIM];
__device__ __align__(16) float d_pool[(size_t)GMAX * DIM];
__device__ float d_gcnt[GMAX];
__device__ int d_deg[NMAX];
__device__ int d_off[NMAX + 1];
__device__ int d_cur[NMAX];
__device__ int d_col[EMAX];
__device__ unsigned long long d_sstate[NB_SCAN];

// ---- helpers ----
__device__ __forceinline__ void red_add_v4(float* p, float4 v) {
    asm volatile("red.global.add.v4.f32 [%0], {%1,%2,%3,%4};"
                 :: "l"(p), "f"(v.x), "f"(v.y), "f"(v.z), "f"(v.w) : "memory");
}
__device__ __forceinline__ unsigned long long pack2(float v) {
    unsigned long long r;
    asm("mov.b64 %0, {%1,%1};" : "=l"(r) : "r"(__float_as_uint(v)));
    return r;
}
__device__ __forceinline__ void unpack2(unsigned long long v, float& lo, float& hi) {
    unsigned int a, b;
    asm("mov.b64 {%0,%1}, %2;" : "=r"(a), "=r"(b) : "l"(v));
    lo = __uint_as_float(a); hi = __uint_as_float(b);
}
#define FMA2(acc, a, b) \
    asm("fma.rn.f32x2 %0, %1, %2, %0;" : "+l"(acc) : "l"(a), "l"(b))

// ---- launch 1: degree count + pool zero + gcnt + scan-state zero ----
__global__ void count_k(const int* __restrict__ ei, int E, int T,
                        const int* __restrict__ batch, int n, int G) {
    int b = blockIdx.x;
    int tid = threadIdx.x;
    int i = b * 256 + tid;
    int e0 = i, e1 = i + T, e2 = i + 2 * T, e3 = i + 3 * T;
    int v0 = (e0 < E) ? __ldg(&ei[E + e0]) : -1;
    int v1 = (e1 < E) ? __ldg(&ei[E + e1]) : -1;
    int v2 = (e2 < E) ? __ldg(&ei[E + e2]) : -1;
    int v3 = (e3 < E) ? __ldg(&ei[E + e3]) : -1;
    if (v0 >= 0) atomicAdd(&d_deg[v0], 1);
    if (v1 >= 0) atomicAdd(&d_deg[v1], 1);
    if (v2 >= 0) atomicAdd(&d_deg[v2], 1);
    if (v3 >= 0) atomicAdd(&d_deg[v3], 1);
    if (b < 128) {
        int j = b * 256 + tid;
        if (j < G * DIM) d_pool[j] = 0.f;
    } else if (b < 130) {
        int g = (b - 128) * 256 + tid;
        if (g < G) {
            int lo = 0, hi = n;
            while (lo < hi) { int m = (lo + hi) >> 1; if (batch[m] < g) lo = m + 1; else hi = m; }
            int lo2 = lo, hi2 = n;
            while (lo2 < hi2) { int m = (lo2 + hi2) >> 1; if (batch[m] < g + 1) lo2 = m + 1; else hi2 = m; }
            d_gcnt[g] = (float)(lo2 - lo);
        }
    } else if (b == 130) {
        d_sstate[tid] = 0ULL;
        d_sstate[tid + 256] = 0ULL;
    }
}

// ---- launch 2: single-pass decoupled-lookback exclusive scan ----
__global__ __launch_bounds__(256)
void scan_lb_k(int n, int E) {
    __shared__ int wsc[8];
    __shared__ int sbase;
    int b = blockIdx.x, tid = threadIdx.x, lane = tid & 31, wid = tid >> 5;
    int i = b * 256 + tid;
    int v = 0;
    if (i < n) { v = d_deg[i]; d_deg[i] = 0; }
    int s = v;
#pragma unroll
    for (int o = 1; o < 32; o <<= 1) {
        int t = __shfl_up_sync(0xffffffffu, s, o);
        if (lane >= o) s += t;
    }
    if (lane == 31) wsc[wid] = s;
    __syncthreads();
    if (wid == 0 && lane < 8) {
        int ws = wsc[lane];
#pragma unroll
        for (int o = 1; o < 8; o <<= 1) {
            int t = __shfl_up_sync(0xffu, ws, o);
            if (lane >= o) ws += t;
        }
        wsc[lane] = ws;
    }
    __syncthreads();
    int incl = s + (wid ? wsc[wid - 1] : 0);
    int total = wsc[7];

    if (tid == 0)
        atomicExch(&d_sstate[b], (b == 0 ? PFX : AGG) | (unsigned long long)(unsigned)total);

    if (b == 0) {
        if (tid == 0) sbase = 0;
    } else if (wid == 0) {
        unsigned long long run = 0;
        int j = b - 1;
        while (true) {
            int idx = j - lane;
            unsigned long long w64 = (idx >= 0) ? atomicAdd(&d_sstate[idx], 0ULL) : PFX;
            while (__ballot_sync(0xffffffffu, w64 == 0ULL)) {
                if (w64 == 0ULL) w64 = atomicAdd(&d_sstate[idx], 0ULL);
            }
            unsigned pm = __ballot_sync(0xffffffffu, (w64 & PFX) != 0ULL);
            unsigned c;
            if (pm) {
                int fp = __ffs(pm) - 1;
                c = (lane <= fp) ? (unsigned)w64 : 0;
#pragma unroll
                for (int o = 16; o; o >>= 1) c += __shfl_xor_sync(0xffffffffu, c, o);
                run += c;
                break;
            } else {
                c = (unsigned)w64;
#pragma unroll
                for (int o = 16; o; o >>= 1) c += __shfl_xor_sync(0xffffffffu, c, o);
                run += c;
                j -= 32;
            }
        }
        if (lane == 0) {
            atomicExch(&d_sstate[b], PFX | (unsigned long long)(unsigned)(run + (unsigned)total));
            sbase = (int)run;
        }
    }
    __syncthreads();
    int base = sbase;
    if (i < n) { int ex = base + incl - v; d_off[i] = ex; d_cur[i] = ex; }
    if (b == 0 && tid == 0) d_off[n] = E;
}

// ---- launch 3: CSR fill ----
__global__ void fill_k(const int* __restrict__ ei, int E, int T) {
    int i = blockIdx.x * blockDim.x + threadIdx.x;
#pragma unroll
    for (int t = 0; t < 4; t++) {
        int e = i + t * T;
        if (e < E) {
            int s = __ldg(&ei[e]);
            int d = __ldg(&ei[E + e]);
            int p = atomicAdd(&d_cur[d], 1);
            d_col[p] = s;
        }
    }
}

// ---- gather: warp per node; idx coalesced + shfl-broadcast; 8-edge batches.
//      launch_bounds(256,7) caps regs at 36 -> 56 warps/SM theoretical (was 48). ----
__global__ __launch_bounds__(256, 7)
void gather_k(const float* __restrict__ feat, float* __restrict__ agg, int N) {
    int node = (blockIdx.x * 256 + threadIdx.x) >> 5;
    int lane = threadIdx.x & 31;
    if (node >= N) return;
    int beg = d_off[node];
    int end = d_off[node + 1];
    int half = lane >> 4;
    int col4 = lane & 15;
    const float4* f4 = (const float4*)feat;
    float4 acc = make_float4(0.f, 0.f, 0.f, 0.f);
    for (int b = beg; b < end; b += 32) {
        int m = min(32, end - b);
        int idx = (lane < m) ? __ldg(&d_col[b + lane]) : 0;
        int j = 0;
        for (; j + 8 <= m; j += 8) {
            int c0 = __shfl_sync(0xffffffffu, idx, j     + half);
            int c1 = __shfl_sync(0xffffffffu, idx, j + 2 + half);
            int c2 = __shfl_sync(0xffffffffu, idx, j + 4 + half);
            int c3 = __shfl_sync(0xffffffffu, idx, j + 6 + half);
            float4 v0 = __ldg(f4 + (size_t)c0 * 16 + col4);
            float4 v1 = __ldg(f4 + (size_t)c1 * 16 + col4);
            float4 v2 = __ldg(f4 + (size_t)c2 * 16 + col4);
            float4 v3 = __ldg(f4 + (size_t)c3 * 16 + col4);
            acc.x += (v0.x + v1.x) + (v2.x + v3.x);
            acc.y += (v0.y + v1.y) + (v2.y + v3.y);
            acc.z += (v0.z + v1.z) + (v2.z + v3.z);
            acc.w += (v0.w + v1.w) + (v2.w + v3.w);
        }
        for (; j + 2 <= m; j += 2) {
            int c = __shfl_sync(0xffffffffu, idx, j + half);
            float4 v = __ldg(f4 + (size_t)c * 16 + col4);
            acc.x += v.x; acc.y += v.y; acc.z += v.z; acc.w += v.w;
        }
        if (j < m) {
            int c = __shfl_sync(0xffffffffu, idx, m - 1);
            if (half == 0) {
                float4 v = __ldg(f4 + (size_t)c * 16 + col4);
                acc.x += v.x; acc.y += v.y; acc.z += v.z; acc.w += v.w;
            }
        }
    }
    acc.x += __shfl_xor_sync(0xffffffffu, acc.x, 16);
    acc.y += __shfl_xor_sync(0xffffffffu, acc.y, 16);
    acc.z += __shfl_xor_sync(0xffffffffu, acc.z, 16);
    acc.w += __shfl_xor_sync(0xffffffffu, acc.w, 16);
    if (half == 0) {
        float inv = 1.f / (float)max(end - beg, 1);
        acc.x *= inv; acc.y *= inv; acc.z *= inv; acc.w *= inv;
        *(float4*)(agg + (size_t)node * DIM + col4 * 4) = acc;
    }
}

// ---- fused SAGE node update, 4-node register tiling (R9 measured-best) ----
__global__ __launch_bounds__(256)
void node_k(const float* __restrict__ xin, const float* __restrict__ agg,
            const float* __restrict__ Wl, const float* __restrict__ bl,
            const float* __restrict__ Wr, float* __restrict__ hout,
            const int* __restrict__ batch, int n_nodes) {
    extern __shared__ __align__(16) float smem[];
    float* wlT = smem;                 // 4096 floats
    float* wrT = smem + 4096;          // 4096
    float* ash = smem + 8192;          // 64 x 64
    float* xsh = smem + 12288;         // 64 x 64

    int tid = threadIdx.x;
    for (int i = tid; i < DIM * DIM; i += 256) {
        int o = i >> 6, k = i & 63;
        int rot = (o + 4 * k) & 63;
        wlT[k * DIM + rot] = Wl[i];
        wrT[k * DIM + rot] = Wr[i];
    }
    {
        int nb = blockIdx.x * 64;
        long long base4 = (long long)nb * 16;
        long long lim = (long long)n_nodes * 16;
        const float4* agg4 = (const float4*)agg;
        const float4* x4   = (const float4*)xin;
        float4 z = make_float4(0.f, 0.f, 0.f, 0.f);
#pragma unroll
        for (int t = 0; t < 4; t++) {
            int i = tid + t * 256;
            long long g = base4 + i;
            ((float4*)ash)[i] = (g < lim) ? agg4[g] : z;
            ((float4*)xsh)[i] = (g < lim) ? x4[g]   : z;
        }
    }
    __syncthreads();

    int q = tid & 15;
    int s = tid >> 4;
    float4 bq = *(const float4*)(bl + 4 * q);

    unsigned long long accl[4][2] = {{0,0},{0,0},{0,0},{0,0}};
    unsigned long long accr[4][2] = {{0,0},{0,0},{0,0},{0,0}};

#pragma unroll 4
    for (int k0 = 0; k0 < DIM; k0 += 4) {
        float av[4][4], xv[4][4];
#pragma unroll
        for (int j = 0; j < 4; j++) {
            *(float4*)av[j] = *(const float4*)&ash[(s + 16 * j) * DIM + k0];
            *(float4*)xv[j] = *(const float4*)&xsh[(s + 16 * j) * DIM + k0];
        }
#pragma unroll
        for (int kk = 0; kk < 4; kk++) {
            int k = k0 + kk;
            int rot = (4 * q + 4 * k) & 63;
            double2 wl = *(const double2*)&wlT[k * DIM + rot];
            double2 wr = *(const double2*)&wrT[k * DIM + rot];
            unsigned long long wlx = __double_as_longlong(wl.x);
            unsigned long long wly = __double_as_longlong(wl.y);
            unsigned long long wrx = __double_as_longlong(wr.x);
            unsigned long long wry = __double_as_longlong(wr.y);
#pragma unroll
            for (int j = 0; j < 4; j++) {
                unsigned long long a2 = pack2(av[j][kk]);
                unsigned long long x2 = pack2(xv[j][kk]);
                FMA2(accl[j][0], a2, wlx);
                FMA2(accl[j][1], a2, wly);
                FMA2(accr[j][0], x2, wrx);
                FMA2(accr[j][1], x2, wry);
            }
        }
    }

    int nb = blockIdx.x * 64;
#pragma unroll
    for (int j = 0; j < 4; j++) {
        int node = nb + s + 16 * j;
        if (node >= n_nodes) continue;
        float l0, l1, l2, l3, r0, r1, r2, r3;
        unpack2(accl[j][0], l0, l1); unpack2(accl[j][1], l2, l3);
        unpack2(accr[j][0], r0, r1); unpack2(accr[j][1], r2, r3);
        float4 res;
        res.x = fmaxf(l0 + r0 + bq.x, 0.f);
        res.y = fmaxf(l1 + r1 + bq.y, 0.f);
        res.z = fmaxf(l2 + r2 + bq.z, 0.f);
        res.w = fmaxf(l3 + r3 + bq.w, 0.f);
        if (batch) {
            int g = batch[node];
            red_add_v4(&d_pool[(size_t)g * DIM + 4 * q], res);
        } else {
            *(float4*)&hout[(size_t)node * DIM + 4 * q] = res;
        }
    }
}
#define NODE_SMEM (16384 * 4)

// ---- pooled mean -> fc -> log_softmax ----
__global__ void final_k(const float* __restrict__ fcW, const float* __restrict__ fcb,
                        float* __restrict__ out, int G) {
    int g = blockIdx.x * blockDim.x + threadIdx.x;
    if (g >= G) return;
    float inv = 1.f / fmaxf(d_gcnt[g], 1.f);
    float p[DIM];
    const float* pr = &d_pool[(size_t)g * DIM];
#pragma unroll
    for (int k = 0; k < DIM; k++) p[k] = pr[k] * inv;
    float lg[ODIM];
#pragma unroll
    for (int o = 0; o < ODIM; o++) {
        float s = fcb[o];
        const float* w = &fcW[o * DIM];
#pragma unroll
        for (int k = 0; k < DIM; k++) s = fmaf(p[k], w[k], s);
        lg[o] = s;
    }
    float m = lg[0];
#pragma unroll
    for (int o = 1; o < ODIM; o++) m = fmaxf(m, lg[o]);
    float se = 0.f;
#pragma unroll
    for (int o = 0; o < ODIM; o++) se += expf(lg[o] - m);
    float lse = m + logf(se);
#pragma unroll
    for (int o = 0; o < ODIM; o++) out[g * ODIM + o] = lg[o] - lse;
}

extern "C" void kernel_launch(void* const* d_in, const int* in_sizes, int n_in,
                              void* d_out, int out_size) {
    const float* x   = (const float*)d_in[0];
    const float* W1l = (const float*)d_in[1];
    const float* b1  = (const float*)d_in[2];
    const float* W1r = (const float*)d_in[3];
    const float* W2l = (const float*)d_in[4];
    const float* b2  = (const float*)d_in[5];
    const float* W2r = (const float*)d_in[6];
    const float* fcW = (const float*)d_in[7];
    const float* fcb = (const float*)d_in[8];
    const int* ei    = (const int*)d_in[9];     // int32 (JAX x64 disabled)
    const int* batch = (const int*)d_in[10];

    int N = in_sizes[10];
    int E = in_sizes[9] / 2;
    int G = out_size / ODIM;
    int NB = (N + 255) / 256;
    int T  = (E + 3) / 4;
    int NBE4 = (T + 255) / 256;

    float *agg, *h1;
    cudaGetSymbolAddress((void**)&agg, d_agg);
    cudaGetSymbolAddress((void**)&h1,  d_h1);

    static int smem_set = 0;   // sticky attribute; host-side, not a graph op
    if (!smem_set) {
        cudaFuncSetAttribute(node_k, cudaFuncAttributeMaxDynamicSharedMemorySize, NODE_SMEM);
        smem_set = 1;
    }

    // CSR build (single-pass lookback scan; invariants restored each replay)
    count_k<<<NBE4, 256>>>(ei, E, T, batch, N, G);   // 1
    scan_lb_k<<<NB, 256>>>(N, E);                    // 2
    fill_k<<<NBE4, 256>>>(ei, E, T);                 // 3

    // layer 1
    gather_k<<<(N + 7) / 8, 256>>>(x, agg, N);       // 4 <- profiled
    node_k<<<(N + 63) / 64, 256, NODE_SMEM>>>(x, agg, W1l, b1, W1r, h1, nullptr, N);  // 5

    // layer 2
    gather_k<<<(N + 7) / 8, 256>>>(h1, agg, N);
    node_k<<<(N + 63) / 64, 256, NODE_SMEM>>>(h1, agg, W2l, b2, W2r, nullptr, batch, N);

    // pool -> fc -> log_softmax
    final_k<<<(G + 255) / 256, 256>>>(fcW, fcb, (float*)d_out, G);
}